// round 14
// baseline (speedup 1.0000x reference)
#include <cuda_runtime.h>
#include <cuda_fp16.h>
#include <cstdint>

#define D 64
#define MAXROWS 616000

// Scratch (device globals: allocation-free rule) — fp16 pre-activations
__device__ __half g_coreh[(size_t)MAXROWS * D];
__device__ __half g_gateh[(size_t)MAXROWS * D];
__device__ float g_stats[4 * D];   // sum_c | sumsq_c | sum_g | sumsq_g
__device__ float g_norm[4 * D];    // scale_c | shift_c | scale_g | shift_g

__device__ __forceinline__ uint32_t f2tf(float f) {
    uint32_t r; asm("cvt.rna.tf32.f32 %0, %1;" : "=r"(r) : "f"(f)); return r;
}
__device__ __forceinline__ float f2tff(float f) { return __uint_as_float(f2tf(f)); }

// tf32 m16n8k8 (used only in rowxform)
__device__ __forceinline__ void mma8(float c[4], const uint32_t a[4], const uint32_t b[2]) {
    asm volatile("mma.sync.aligned.m16n8k8.row.col.f32.tf32.tf32.f32 "
        "{%0,%1,%2,%3}, {%4,%5,%6,%7}, {%8,%9}, {%0,%1,%2,%3};\n"
        : "+f"(c[0]), "+f"(c[1]), "+f"(c[2]), "+f"(c[3])
        : "r"(a[0]), "r"(a[1]), "r"(a[2]), "r"(a[3]), "r"(b[0]), "r"(b[1]));
}

// fp16 m16n8k16, fp32 accum
__device__ __forceinline__ void mma16(float c[4], const uint32_t a[4], const uint32_t b[2]) {
    asm volatile("mma.sync.aligned.m16n8k16.row.col.f32.f16.f16.f32 "
        "{%0,%1,%2,%3}, {%4,%5,%6,%7}, {%8,%9}, {%0,%1,%2,%3};\n"
        : "+f"(c[0]), "+f"(c[1]), "+f"(c[2]), "+f"(c[3])
        : "r"(a[0]), "r"(a[1]), "r"(a[2]), "r"(a[3]), "r"(b[0]), "r"(b[1]));
}

__device__ __forceinline__ uint32_t packh2(float x, float y) {
    __half2 h = __floats2half2_rn(x, y);
    return *reinterpret_cast<uint32_t*>(&h);
}

__device__ __forceinline__ void cpasync16(void* smem_dst, const void* gmem_src, int sz) {
    uint32_t d = (uint32_t)__cvta_generic_to_shared(smem_dst);
    asm volatile("cp.async.ca.shared.global [%0], [%1], 16, %2;"
                 :: "r"(d), "l"(gmem_src), "r"(sz));
}

// ---------------------------------------------------------------------------
// Pass 1: direct-LDG gather -> register fp16 convert -> swizzled STS,
// double-buffered fp16 tiles on a GLOBAL chunk counter (seamless across
// tiles), ONE barrier per chunk, ldmatrix A fragments, dual fp16 GEMM
// (core|gate) + per-feature stats.
// sIdx double-buffered: tile t+1's indices loaded at tile t's q==0
// (published by the q==1 barrier); tile t+1's chunk-0 GATHER is issued at
// tile t's last chunk, so the LDG stream never drains at tile boundaries.
// Safety: push(c) overwrites the buffer last read by mma(c-2), proven
// complete by barrier(c-1) — invariant holds across tile boundaries.
// Block = 256 threads (8 warps), 2 blocks/SM. Tile = 64 rows x 128 cols.
// ---------------------------------------------------------------------------
template<int K, int NSEG>
__global__ void __launch_bounds__(256, 2) pass1_mma(
    const float* __restrict__ b0, const int* __restrict__ i0,
    const float* __restrict__ b1, const int* __restrict__ i1,
    const float* __restrict__ b2, const int* __restrict__ i2,
    const float* __restrict__ b3, const int* __restrict__ i3,
    const float* __restrict__ Wc, const float* __restrict__ Wg,
    int R)
{
    extern __shared__ float smem[];
    __half2* sWh  = (__half2*)smem;                   // (K/2)*128 half2 = K*64 floats
    __half2* sH   = (__half2*)(smem + K * 64);        // 2 * 64*32 half2 tiles
    int*     sIdx = (int*)(smem + K * 64 + 2 * 2048); // 2 * 256 (double buffer)
    float*   sStat = (float*)(sIdx + 512);            // 256

    const int tid  = threadIdx.x;
    const int lane = tid & 31, wid = tid >> 5;
    const int wr = wid >> 2, wc = wid & 3;
    const int g = lane >> 2, t = lane & 3;

    // Pack combined weights (core|gate) as k-interleaved fp16, swizzled
    for (int idx = tid; idx < (K / 2) * 128; idx += 256) {
        int k2 = idx >> 7, n = idx & 127;
        float f0, f1;
        if (n < 64) { f0 = Wc[(2 * k2) * 64 + n];        f1 = Wc[(2 * k2 + 1) * 64 + n]; }
        else        { f0 = Wg[(2 * k2) * 64 + (n - 64)]; f1 = Wg[(2 * k2 + 1) * 64 + (n - 64)]; }
        sWh[k2 * 128 + (n ^ ((k2 & 3) << 3))] = __floats2half2_rn(f0, f1);
    }
    sStat[tid] = 0.f;

    const float* bps[4] = {b0, b1, b2, b3};
    const uint32_t sHaddr = (uint32_t)__cvta_generic_to_shared(sH);

    // gather mapping: thread covers row irow (0..63), 16 contiguous floats
    const int irow = tid >> 2;
    const int if4  = tid & 3;

    auto loadIdxTo = [&](int tile, int* buf) {
        if (tid < NSEG * 64) {
            int s = tid >> 6, r = tid & 63;
            int grow = (tile << 6) + r;
            const int* ip = (s == 0) ? i0 : (s == 1) ? i1 : (s == 2) ? i2 : i3;
            int srow = -1;
            if (grow < R) srow = ip ? ip[grow] : grow;
            buf[tid] = srow;
        }
    };

    auto fetch = [&](const int* idxb, int s, float4 v[4]) {
        int srow = idxb[s * 64 + irow];
        const float* src = bps[s] + (size_t)(srow < 0 ? 0 : srow) * D + if4 * 16;
        #pragma unroll
        for (int i = 0; i < 4; i++) v[i] = *reinterpret_cast<const float4*>(src + i * 4);
        if (srow < 0) {
            #pragma unroll
            for (int i = 0; i < 4; i++) v[i] = make_float4(0.f, 0.f, 0.f, 0.f);
        }
    };

    auto push = [&](const float4 v[4], int buf) {
        uint32_t h[8];
        #pragma unroll
        for (int i = 0; i < 4; i++) {
            h[2 * i]     = packh2(v[i].x, v[i].y);
            h[2 * i + 1] = packh2(v[i].z, v[i].w);
        }
        const int sw = (irow & 7) << 2;
        uint32_t* dst = reinterpret_cast<uint32_t*>(sH + buf * 2048) + irow * 32;
        *reinterpret_cast<uint4*>(dst + ((if4 * 8) ^ sw)) =
            make_uint4(h[0], h[1], h[2], h[3]);
        *reinterpret_cast<uint4*>(dst + ((if4 * 8 + 4) ^ sw)) =
            make_uint4(h[4], h[5], h[6], h[7]);
    };

    float ssum[8] = {0,0,0,0,0,0,0,0};
    float ssq[8]  = {0,0,0,0,0,0,0,0};

    // ldmatrix lane-address components (constant per thread)
    const int lmRowOff = ((lane >> 3) & 1) * 8 + (lane & 7);
    const int lmUnitOff = ((lane >> 4) & 1) * 4;

    const int ntiles = (R + 63) >> 6;
    int tp = 0;           // sIdx parity
    unsigned c = 0;       // global chunk counter (fp16 buffer parity)

    // Prologue: indices + first gather for the first tile
    if ((int)blockIdx.x < ntiles) loadIdxTo(blockIdx.x, sIdx);
    __syncthreads();   // publishes sW, sStat, first sIdx

    float4 vreg[2][4];
    if ((int)blockIdx.x < ntiles) fetch(sIdx, 0, vreg[0]);

    for (int tile = blockIdx.x; tile < ntiles; tile += gridDim.x, tp ^= 1) {
        const int base = tile << 6;
        const int tnext = tile + gridDim.x;
        const int* idxb  = sIdx + tp * 256;
        const int* idxbn = sIdx + (tp ^ 1) * 256;

        float acc[2][4][4];
        #pragma unroll
        for (int ss = 0; ss < 2; ss++)
            #pragma unroll
            for (int nt = 0; nt < 4; nt++)
                #pragma unroll
                for (int i = 0; i < 4; i++) acc[ss][nt][i] = 0.f;

        #pragma unroll
        for (int q = 0; q < NSEG; q++, c++) {
            if (q + 1 < NSEG)           fetch(idxb, q + 1, vreg[(c + 1) & 1]);
            else if (tnext < ntiles)    fetch(idxbn, 0, vreg[(c + 1) & 1]);   // cross-tile
            push(vreg[c & 1], c & 1);
            __syncthreads();   // publishes fp16 chunk c; proves mma(c-1) done
            if (q == 0 && tnext < ntiles)
                loadIdxTo(tnext, sIdx + (tp ^ 1) * 256);  // published by q=1 barrier

            const uint32_t bufb = sHaddr + (c & 1) * 2048 * 4;
            const int k2base = q * 32;

            #pragma unroll
            for (int kg = 0; kg < 4; kg++) {
                const int ku = kg * 8;
                uint32_t a[2][4];
                #pragma unroll
                for (int ss = 0; ss < 2; ss++) {
                    int mrow = wr * 32 + ss * 16 + lmRowOff;
                    int ub   = ku + lmUnitOff;
                    uint32_t addr = bufb + (uint32_t)(mrow * 32 + (ub ^ ((mrow & 7) << 2))) * 4;
                    asm volatile("ldmatrix.sync.aligned.m8n8.x4.shared.b16 "
                                 "{%0,%1,%2,%3}, [%4];"
                                 : "=r"(a[ss][0]), "=r"(a[ss][1]),
                                   "=r"(a[ss][2]), "=r"(a[ss][3])
                                 : "r"(addr));
                }
                const uint32_t* pw = reinterpret_cast<const uint32_t*>(sWh);
                #pragma unroll
                for (int nt = 0; nt < 4; nt++) {
                    int c0 = (wc * 32 + nt * 8 + g) ^ (t << 3);
                    uint32_t b[2];
                    b[0] = pw[(k2base + ku + t) * 128 + c0];
                    b[1] = pw[(k2base + ku + t + 4) * 128 + c0];
                    mma16(acc[0][nt], a[0], b);
                    mma16(acc[1][nt], a[1], b);
                }
            }
        }

        // Epilogue: fp16 stores + stats (tail rows carry zero accs);
        // runs while next tile's chunk-0 gather is already in flight.
        #pragma unroll
        for (int ss = 0; ss < 2; ss++) {
            int row0 = base + wr * 32 + ss * 16 + g;
            #pragma unroll
            for (int nt = 0; nt < 4; nt++) {
                int col = wc * 32 + nt * 8 + 2 * t;
                __half* outp = (col < 64) ? g_coreh : g_gateh;
                int ocol = col & 63;
                if (row0 < R)
                    *reinterpret_cast<__half2*>(&outp[(size_t)row0 * D + ocol]) =
                        __floats2half2_rn(acc[ss][nt][0], acc[ss][nt][1]);
                if (row0 + 8 < R)
                    *reinterpret_cast<__half2*>(&outp[(size_t)(row0 + 8) * D + ocol]) =
                        __floats2half2_rn(acc[ss][nt][2], acc[ss][nt][3]);
                ssum[nt * 2 + 0] += acc[ss][nt][0] + acc[ss][nt][2];
                ssum[nt * 2 + 1] += acc[ss][nt][1] + acc[ss][nt][3];
                ssq[nt * 2 + 0]  += acc[ss][nt][0] * acc[ss][nt][0]
                                  + acc[ss][nt][2] * acc[ss][nt][2];
                ssq[nt * 2 + 1]  += acc[ss][nt][1] * acc[ss][nt][1]
                                  + acc[ss][nt][3] * acc[ss][nt][3];
            }
        }
    }

    #pragma unroll
    for (int j = 0; j < 8; j++) {
        int col = wc * 32 + (j >> 1) * 8 + 2 * t + (j & 1);
        int sb  = (col < 64) ? 0 : 128;
        int oc  = col & 63;
        atomicAdd(&sStat[sb + oc], ssum[j]);
        atomicAdd(&sStat[sb + 64 + oc], ssq[j]);
    }
    __syncthreads();
    atomicAdd(&g_stats[tid], sStat[tid]);
}

// ---------------------------------------------------------------------------
// Finalize BN scale/shift (1 block, 128 threads); self-zeroes g_stats.
// ---------------------------------------------------------------------------
__global__ void finalize_kernel(const float* __restrict__ gc, const float* __restrict__ bc,
                                const float* __restrict__ gg, const float* __restrict__ bg,
                                float invR)
{
    int t = threadIdx.x;
    if (t < 64) {
        float mean = g_stats[t] * invR;
        float var  = fmaxf(g_stats[64 + t] * invR - mean * mean, 0.f);
        float sc   = gc[t] * rsqrtf(var + 1e-5f);
        g_norm[t]      = sc;
        g_norm[64 + t] = bc[t] - mean * sc;
        g_stats[t] = 0.f;
        g_stats[64 + t] = 0.f;
    } else {
        int c = t - 64;
        float mean = g_stats[128 + c] * invR;
        float var  = fmaxf(g_stats[192 + c] * invR - mean * mean, 0.f);
        float sc   = gg[c] * rsqrtf(var + 1e-5f);
        g_norm[128 + c] = sc;
        g_norm[192 + c] = bg[c] - mean * sc;
        g_stats[128 + c] = 0.f;
        g_stats[192 + c] = 0.f;
    }
}

__device__ __forceinline__ float sigm(float x) { return 1.f / (1.f + __expf(-x)); }

__device__ __forceinline__ void unpack8(uint4 r, float o[8]) {
    __half2 h0 = *reinterpret_cast<__half2*>(&r.x);
    __half2 h1 = *reinterpret_cast<__half2*>(&r.y);
    __half2 h2 = *reinterpret_cast<__half2*>(&r.z);
    __half2 h3 = *reinterpret_cast<__half2*>(&r.w);
    float2 f0 = __half22float2(h0), f1 = __half22float2(h1);
    float2 f2 = __half22float2(h2), f3 = __half22float2(h3);
    o[0] = f0.x; o[1] = f0.y; o[2] = f1.x; o[3] = f1.y;
    o[4] = f2.x; o[5] = f2.y; o[6] = f3.x; o[7] = f3.y;
}

// ---------------------------------------------------------------------------
// BN + silu*sigmoid + vectorized atomic segment scatter (v4 red)
// ---------------------------------------------------------------------------
__global__ void apply_scatter_kernel(const int* __restrict__ seg, float* __restrict__ S, int R)
{
    int idx = blockIdx.x * blockDim.x + threadIdx.x;
    if (idx >= R * 8) return;
    int row = idx >> 3;
    int col = (idx & 7) * 8;
    int s = seg[row];                    // hoisted independent long-latency load
    uint4 cr = *reinterpret_cast<const uint4*>(g_coreh + (size_t)row * D + col);
    uint4 gr = *reinterpret_cast<const uint4*>(g_gateh + (size_t)row * D + col);

    float cs[8], gs[8];
    unpack8(cr, cs);
    unpack8(gr, gs);

    float m[8];
    #pragma unroll
    for (int j = 0; j < 8; j++) {
        int cc = col + j;
        float cn = cs[j] * g_norm[cc]       + g_norm[64 + cc];
        float gn = gs[j] * g_norm[128 + cc] + g_norm[192 + cc];
        m[j] = cn * sigm(cn) * sigm(gn);
    }
    float* dst = S + (size_t)s * D + col;
    asm volatile("red.global.add.v4.f32 [%0], {%1,%2,%3,%4};"
                 :: "l"(dst), "f"(m[0]), "f"(m[1]), "f"(m[2]), "f"(m[3]) : "memory");
    asm volatile("red.global.add.v4.f32 [%0], {%1,%2,%3,%4};"
                 :: "l"(dst + 4), "f"(m[4]), "f"(m[5]), "f"(m[6]), "f"(m[7]) : "memory");
}

// ---------------------------------------------------------------------------
// BN + silu*sigmoid + residual write (angle stage)
// ---------------------------------------------------------------------------
__global__ void apply_write_kernel(const float* __restrict__ angle, float* __restrict__ dst, int R)
{
    int idx = blockIdx.x * blockDim.x + threadIdx.x;
    if (idx >= R * 8) return;
    int row = idx >> 3;
    int col = (idx & 7) * 8;
    uint4 cr = *reinterpret_cast<const uint4*>(g_coreh + (size_t)row * D + col);
    uint4 gr = *reinterpret_cast<const uint4*>(g_gateh + (size_t)row * D + col);
    float4 a0 = *reinterpret_cast<const float4*>(angle + (size_t)row * D + col);
    float4 a1 = *reinterpret_cast<const float4*>(angle + (size_t)row * D + col + 4);

    float cs[8], gs[8];
    unpack8(cr, cs);
    unpack8(gr, gs);
    float av[8] = {a0.x, a0.y, a0.z, a0.w, a1.x, a1.y, a1.z, a1.w};

    float o[8];
    #pragma unroll
    for (int j = 0; j < 8; j++) {
        int cc = col + j;
        float cn = cs[j] * g_norm[cc]       + g_norm[64 + cc];
        float gn = gs[j] * g_norm[128 + cc] + g_norm[192 + cc];
        o[j] = cn * sigm(cn) * sigm(gn) + av[j];
    }
    *reinterpret_cast<float4*>(dst + (size_t)row * D + col) =
        make_float4(o[0], o[1], o[2], o[3]);
    *reinterpret_cast<float4*>(dst + (size_t)row * D + col + 4) =
        make_float4(o[4], o[5], o[6], o[7]);
}

// ---------------------------------------------------------------------------
// Row transform v3 (persistent, cp.async 3-slot ring with 2-deep prologue):
// S[tile,:] = S[tile,:] @ W(64x64) + resid.
// ---------------------------------------------------------------------------
__global__ void __launch_bounds__(256, 2) rowxform_mma(
    float* __restrict__ S, const float* __restrict__ W,
    const float* __restrict__ resid, int R)
{
    extern __shared__ float smem[];
    float* sW2 = smem;              // 64*64
    float* sX  = smem + 64 * 64;    // 3 * 64*64

    const int tid  = threadIdx.x;
    const int lane = tid & 31, wid = tid >> 5;
    const int wr = wid >> 1, wc = wid & 1;
    const int g = lane >> 2, t = lane & 3;

    for (int idx = tid; idx < 64 * 64; idx += 256) {
        int k = idx >> 6, c = idx & 63;
        sW2[k * 64 + (c ^ ((k & 3) << 3))] = f2tff(W[idx]);
    }

    // fetch mapping: thread covers row irow (0..63), 16 contiguous floats
    const int irow = tid >> 2;
    const int if4  = tid & 3;
    const int sw   = (irow & 7) << 2;

    auto issue = [&](int tile, int slot) {
        int grow = (tile << 6) + irow;
        int sz = (grow < R) ? 16 : 0;
        const float* src = S + (size_t)(grow < R ? grow : 0) * D + if4 * 16;
        float* dstb = sX + slot * 4096 + irow * 64;
        #pragma unroll
        for (int i = 0; i < 4; i++) {
            int f = if4 * 16 + i * 4;
            cpasync16(&dstb[f ^ sw], src + i * 4, sz);
        }
        asm volatile("cp.async.commit_group;");
    };

    const int ntiles = (R + 63) >> 6;
    int tile = blockIdx.x;
    if (tile < ntiles) issue(tile, 0);
    if (tile + gridDim.x < ntiles) issue(tile + gridDim.x, 1);

    unsigned it = 0;
    for (; tile < ntiles; tile += gridDim.x, it++) {
        const int base = tile << 6;
        const bool more1 = (tile + (int)gridDim.x) < ntiles;       // tile it+1 exists
        const bool more2 = (tile + 2 * (int)gridDim.x) < ntiles;   // tile it+2 exists

        if (more1) { asm volatile("cp.async.wait_group 1;"); }
        else       { asm volatile("cp.async.wait_group 0;"); }
        __syncthreads();   // publish tile it (+ sW2 on it==0); prove mma it-1 consumed
        if (more2) issue(tile + 2 * gridDim.x, (it + 2) % 3);

        const float* sB = sX + (it % 3) * 4096;

        float acc[4][4];
        #pragma unroll
        for (int nt = 0; nt < 4; nt++)
            #pragma unroll
            for (int i = 0; i < 4; i++) acc[nt][i] = 0.f;

        #pragma unroll
        for (int k0 = 0; k0 < 64; k0 += 8) {
            uint32_t a[4];
            int r0 = wr * 16 + g;
            int sw2 = (r0 & 7) << 2;
            const float* pa = &sB[r0 * 64];
            a[0] = __float_as_uint(pa[(k0 + t) ^ sw2]);
            a[1] = __float_as_uint(pa[8 * 64 + ((k0 + t) ^ sw2)]);
            a[2] = __float_as_uint(pa[(k0 + t + 4) ^ sw2]);
            a[3] = __float_as_uint(pa[8 * 64 + ((k0 + t + 4) ^ sw2)]);
            #pragma unroll
            for (int nt = 0; nt < 4; nt++) {
                int c0 = (wc * 32 + nt * 8 + g) ^ (t << 3);
                uint32_t b[2];
                b[0] = __float_as_uint(sW2[(k0 + t) * 64 + c0]);
                b[1] = __float_as_uint(sW2[(k0 + t + 4) * 64 + c0]);
                mma8(acc[nt], a, b);
            }
        }

        int row0 = base + wr * 16 + g;
        #pragma unroll
        for (int nt = 0; nt < 4; nt++) {
            int col = wc * 32 + nt * 8 + 2 * t;
            if (row0 < R) {
                float2 rr = *reinterpret_cast<const float2*>(&resid[(size_t)row0 * D + col]);
                *reinterpret_cast<float2*>(&S[(size_t)row0 * D + col]) =
                    make_float2(acc[nt][0] + rr.x, acc[nt][1] + rr.y);
            }
            if (row0 + 8 < R) {
                float2 rr = *reinterpret_cast<const float2*>(&resid[(size_t)(row0 + 8) * D + col]);
                *reinterpret_cast<float2*>(&S[(size_t)(row0 + 8) * D + col]) =
                    make_float2(acc[nt][2] + rr.x, acc[nt][3] + rr.y);
            }
        }
    }
}

// ---------------------------------------------------------------------------
// Host orchestration
// ---------------------------------------------------------------------------
extern "C" void kernel_launch(void* const* d_in, const int* in_sizes, int n_in,
                              void* d_out, int out_size)
{
    const bool dictOrder = (n_in >= 4) && (in_sizes[3] > 100000);

    const float *vfeat = (const float*)d_in[0];
    const float *efeat = (const float*)d_in[1];
    const float *afeat = (const float*)d_in[2];
    const float *WcA, *WgA, *WoA, *WcB, *WgB, *WoB, *WcC, *WgC;
    const float *gac, *bac, *gag, *bag, *gbc, *bbc, *gbg, *bbg, *gnc, *bnc, *gng, *bng;
    const int *eidx, *kidx, *iidx, *jidx;

    if (dictOrder) {
        eidx = (const int*)d_in[3];  kidx = (const int*)d_in[4];
        iidx = (const int*)d_in[5];  jidx = (const int*)d_in[6];
        WcA = (const float*)d_in[7];  WgA = (const float*)d_in[8];  WoA = (const float*)d_in[9];
        WcB = (const float*)d_in[10]; WgB = (const float*)d_in[11]; WoB = (const float*)d_in[12];
        WcC = (const float*)d_in[13]; WgC = (const float*)d_in[14];
        gac = (const float*)d_in[15]; gag = (const float*)d_in[16];
        gbc = (const float*)d_in[17]; gbg = (const float*)d_in[18];
        gnc = (const float*)d_in[19]; gng = (const float*)d_in[20];
        bac = (const float*)d_in[21]; bag = (const float*)d_in[22];
        bbc = (const float*)d_in[23]; bbg = (const float*)d_in[24];
        bnc = (const float*)d_in[25]; bng = (const float*)d_in[26];
    } else {
        WcA = (const float*)d_in[3];  WgA = (const float*)d_in[4];  WoA = (const float*)d_in[5];
        WcB = (const float*)d_in[6];  WgB = (const float*)d_in[7];  WoB = (const float*)d_in[8];
        WcC = (const float*)d_in[9];  WgC = (const float*)d_in[10];
        gac = (const float*)d_in[11]; bac = (const float*)d_in[12];
        gag = (const float*)d_in[13]; bag = (const float*)d_in[14];
        gbc = (const float*)d_in[15]; bbc = (const float*)d_in[16];
        gbg = (const float*)d_in[17]; bbg = (const float*)d_in[18];
        gnc = (const float*)d_in[19]; bnc = (const float*)d_in[20];
        gng = (const float*)d_in[21]; bng = (const float*)d_in[22];
        eidx = (const int*)d_in[23]; kidx = (const int*)d_in[24];
        iidx = (const int*)d_in[25]; jidx = (const int*)d_in[26];
    }

    const int N = in_sizes[0] / 64;
    const int E = in_sizes[1] / 64;
    const int T = in_sizes[2] / 64;
    const int* src = eidx;
    const int* dst = eidx + E;

    float* out  = (float*)d_out;
    float* vnew = out;                          // [N,64]
    float* enew = out + (size_t)N * 64;         // [E,64]
    float* anew = out + (size_t)(N + E) * 64;   // [T,64]

    float* stats_ptr = nullptr;
    cudaGetSymbolAddress((void**)&stats_ptr, g_stats);

    int dev = 0;  cudaGetDevice(&dev);
    int sm = 148; cudaDeviceGetAttribute(&sm, cudaDevAttrMultiProcessorCount, dev);

    // pass1 smem floats: K*64 (weights half2) + 2*2048 (fp16 ring) + 512 + 256
    const size_t smemA = (size_t)(192 * 64 + 2 * 2048 + 512 + 256) * 4; // 68,608 B
    const size_t smemB = (size_t)(256 * 64 + 2 * 2048 + 512 + 256) * 4; // 84,992 B
    cudaFuncSetAttribute(pass1_mma<192, 3>, cudaFuncAttributeMaxDynamicSharedMemorySize, (int)smemA);
    cudaFuncSetAttribute(pass1_mma<256, 4>, cudaFuncAttributeMaxDynamicSharedMemorySize, (int)smemB);

    // rowxform smem: (64*64 + 3*64*64) floats = 65,536 B
    const size_t smemR = (size_t)(4 * 64 * 64) * 4;
    cudaFuncSetAttribute(rowxform_mma, cudaFuncAttributeMaxDynamicSharedMemorySize, (int)smemR);

    // One contiguous memset for both segment-sum accumulators (vnew|enew),
    // and one for g_stats (finalize self-zeroes it between stages).
    cudaMemsetAsync(vnew, 0, (size_t)(N + E) * 64 * sizeof(float));
    cudaMemsetAsync(stats_ptr, 0, 256 * sizeof(float));

    // ---------------- Stage A: AtomConvCat ----------------
    pass1_mma<192, 3><<<sm * 2, 256, smemA>>>(
        vfeat, src, efeat, nullptr, vfeat, dst, nullptr, nullptr, WcA, WgA, E);
    finalize_kernel<<<1, 128>>>(gac, bac, gag, bag, 1.f / (float)E);
    apply_scatter_kernel<<<(E * 8 + 255) / 256, 256>>>(src, vnew, E);
    rowxform_mma<<<sm * 2, 256, smemR>>>(vnew, WoA, vfeat, N);

    // ---------------- Stage B: BondConvCat ----------------
    pass1_mma<256, 4><<<sm * 2, 256, smemB>>>(
        vnew, jidx, efeat, kidx, efeat, iidx, afeat, nullptr, WcB, WgB, T);
    finalize_kernel<<<1, 128>>>(gbc, bbc, gbg, bbg, 1.f / (float)T);
    apply_scatter_kernel<<<(T * 8 + 255) / 256, 256>>>(kidx, enew, T);
    rowxform_mma<<<sm * 2, 256, smemR>>>(enew, WoB, efeat, E);

    // ---------------- Stage C: AngleConvCat ----------------
    pass1_mma<256, 4><<<sm * 2, 256, smemB>>>(
        vnew, jidx, enew, kidx, enew, iidx, afeat, nullptr, WcC, WgC, T);
    finalize_kernel<<<1, 128>>>(gnc, bnc, gng, bng, 1.f / (float)T);
    apply_write_kernel<<<(T * 8 + 255) / 256, 256>>>(afeat, anew, T);
}

// round 15
// speedup vs baseline: 1.0830x; 1.0830x over previous
#include <cuda_runtime.h>
#include <cuda_fp16.h>
#include <cstdint>

#define D 64
#define MAXROWS 616000

// Scratch (device globals: allocation-free rule) — fp16 pre-activations
__device__ __half g_coreh[(size_t)MAXROWS * D];
__device__ __half g_gateh[(size_t)MAXROWS * D];
__device__ float g_stats[4 * D];   // sum_c | sumsq_c | sum_g | sumsq_g
__device__ float g_norm[4 * D];    // scale_c | shift_c | scale_g | shift_g

__device__ __forceinline__ uint32_t f2tf(float f) {
    uint32_t r; asm("cvt.rna.tf32.f32 %0, %1;" : "=r"(r) : "f"(f)); return r;
}
__device__ __forceinline__ float f2tff(float f) { return __uint_as_float(f2tf(f)); }

// tf32 m16n8k8 (used only in rowxform)
__device__ __forceinline__ void mma8(float c[4], const uint32_t a[4], const uint32_t b[2]) {
    asm volatile("mma.sync.aligned.m16n8k8.row.col.f32.tf32.tf32.f32 "
        "{%0,%1,%2,%3}, {%4,%5,%6,%7}, {%8,%9}, {%0,%1,%2,%3};\n"
        : "+f"(c[0]), "+f"(c[1]), "+f"(c[2]), "+f"(c[3])
        : "r"(a[0]), "r"(a[1]), "r"(a[2]), "r"(a[3]), "r"(b[0]), "r"(b[1]));
}

// fp16 m16n8k16, fp32 accum
__device__ __forceinline__ void mma16(float c[4], const uint32_t a[4], const uint32_t b[2]) {
    asm volatile("mma.sync.aligned.m16n8k16.row.col.f32.f16.f16.f32 "
        "{%0,%1,%2,%3}, {%4,%5,%6,%7}, {%8,%9}, {%0,%1,%2,%3};\n"
        : "+f"(c[0]), "+f"(c[1]), "+f"(c[2]), "+f"(c[3])
        : "r"(a[0]), "r"(a[1]), "r"(a[2]), "r"(a[3]), "r"(b[0]), "r"(b[1]));
}

__device__ __forceinline__ uint32_t packh2(float x, float y) {
    __half2 h = __floats2half2_rn(x, y);
    return *reinterpret_cast<uint32_t*>(&h);
}

__device__ __forceinline__ void cpasync16(void* smem_dst, const void* gmem_src, int sz) {
    uint32_t d = (uint32_t)__cvta_generic_to_shared(smem_dst);
    asm volatile("cp.async.ca.shared.global [%0], [%1], 16, %2;"
                 :: "r"(d), "l"(gmem_src), "r"(sz));
}

// ---------------------------------------------------------------------------
// Pass 1 (R13 winner + L2 prefetch of next tile's chunk-0 gather):
// direct-LDG gather -> register fp16 convert -> swizzled STS, double-buffered
// fp16 tiles, ONE barrier per chunk, ldmatrix A fragments, dual fp16 GEMM
// (core|gate) + per-feature stats.
// sIdx double-buffered: tile t+1's indices loaded at tile t's q==0
// (published by the q==1 barrier). At the LAST chunk, next tile's chunk-0
// gather lines are prefetched into L2 (no dest registers, no liveness cost).
// Block = 256 threads (8 warps), 2 blocks/SM. Tile = 64 rows x 128 cols.
// ---------------------------------------------------------------------------
template<int K, int NSEG>
__global__ void __launch_bounds__(256, 2) pass1_mma(
    const float* __restrict__ b0, const int* __restrict__ i0,
    const float* __restrict__ b1, const int* __restrict__ i1,
    const float* __restrict__ b2, const int* __restrict__ i2,
    const float* __restrict__ b3, const int* __restrict__ i3,
    const float* __restrict__ Wc, const float* __restrict__ Wg,
    int R)
{
    extern __shared__ float smem[];
    __half2* sWh  = (__half2*)smem;                   // (K/2)*128 half2 = K*64 floats
    __half2* sH   = (__half2*)(smem + K * 64);        // 2 * 64*32 half2 tiles
    int*     sIdx = (int*)(smem + K * 64 + 2 * 2048); // 2 * 256 (double buffer)
    float*   sStat = (float*)(sIdx + 512);            // 256

    const int tid  = threadIdx.x;
    const int lane = tid & 31, wid = tid >> 5;
    const int wr = wid >> 2, wc = wid & 3;
    const int g = lane >> 2, t = lane & 3;

    // Pack combined weights (core|gate) as k-interleaved fp16, swizzled
    for (int idx = tid; idx < (K / 2) * 128; idx += 256) {
        int k2 = idx >> 7, n = idx & 127;
        float f0, f1;
        if (n < 64) { f0 = Wc[(2 * k2) * 64 + n];        f1 = Wc[(2 * k2 + 1) * 64 + n]; }
        else        { f0 = Wg[(2 * k2) * 64 + (n - 64)]; f1 = Wg[(2 * k2 + 1) * 64 + (n - 64)]; }
        sWh[k2 * 128 + (n ^ ((k2 & 3) << 3))] = __floats2half2_rn(f0, f1);
    }
    sStat[tid] = 0.f;

    const float* bps[4] = {b0, b1, b2, b3};
    const uint32_t sHaddr = (uint32_t)__cvta_generic_to_shared(sH);

    // gather mapping: thread covers row irow (0..63), 16 contiguous floats
    const int irow = tid >> 2;
    const int if4  = tid & 3;

    auto loadIdxTo = [&](int tile, int* buf) {
        if (tid < NSEG * 64) {
            int s = tid >> 6, r = tid & 63;
            int grow = (tile << 6) + r;
            const int* ip = (s == 0) ? i0 : (s == 1) ? i1 : (s == 2) ? i2 : i3;
            int srow = -1;
            if (grow < R) srow = ip ? ip[grow] : grow;
            buf[tid] = srow;
        }
    };

    auto fetch = [&](const int* idxb, int s, float4 v[4]) {
        int srow = idxb[s * 64 + irow];
        const float* src = bps[s] + (size_t)(srow < 0 ? 0 : srow) * D + if4 * 16;
        #pragma unroll
        for (int i = 0; i < 4; i++) v[i] = *reinterpret_cast<const float4*>(src + i * 4);
        if (srow < 0) {
            #pragma unroll
            for (int i = 0; i < 4; i++) v[i] = make_float4(0.f, 0.f, 0.f, 0.f);
        }
    };

    auto push = [&](const float4 v[4], int buf) {
        uint32_t h[8];
        #pragma unroll
        for (int i = 0; i < 4; i++) {
            h[2 * i]     = packh2(v[i].x, v[i].y);
            h[2 * i + 1] = packh2(v[i].z, v[i].w);
        }
        const int sw = (irow & 7) << 2;
        uint32_t* dst = reinterpret_cast<uint32_t*>(sH + buf * 2048) + irow * 32;
        *reinterpret_cast<uint4*>(dst + ((if4 * 8) ^ sw)) =
            make_uint4(h[0], h[1], h[2], h[3]);
        *reinterpret_cast<uint4*>(dst + ((if4 * 8 + 4) ^ sw)) =
            make_uint4(h[4], h[5], h[6], h[7]);
    };

    float ssum[8] = {0,0,0,0,0,0,0,0};
    float ssq[8]  = {0,0,0,0,0,0,0,0};

    // ldmatrix lane-address components (constant per thread)
    const int lmRowOff = ((lane >> 3) & 1) * 8 + (lane & 7);
    const int lmUnitOff = ((lane >> 4) & 1) * 4;

    const int ntiles = (R + 63) >> 6;
    int tp = 0;   // sIdx parity: tile uses sIdx + tp*256

    // Prologue: indices for the first tile (covered by the same barrier as sW)
    if ((int)blockIdx.x < ntiles) loadIdxTo(blockIdx.x, sIdx);
    __syncthreads();   // publishes sW, sStat, and first sIdx

    for (int tile = blockIdx.x; tile < ntiles; tile += gridDim.x, tp ^= 1) {
        const int base = tile << 6;
        const int tnext = tile + gridDim.x;
        const int* idxb  = sIdx + tp * 256;
        const int* idxbn = sIdx + (tp ^ 1) * 256;

        float4 vreg[2][4];
        fetch(idxb, 0, vreg[0]);

        float acc[2][4][4];
        #pragma unroll
        for (int ss = 0; ss < 2; ss++)
            #pragma unroll
            for (int nt = 0; nt < 4; nt++)
                #pragma unroll
                for (int i = 0; i < 4; i++) acc[ss][nt][i] = 0.f;

        #pragma unroll
        for (int q = 0; q < NSEG; q++) {
            if (q + 1 < NSEG) fetch(idxb, q + 1, vreg[(q + 1) & 1]);
            push(vreg[q & 1], q & 1);
            __syncthreads();   // publishes fp16 tile q; proves mma(q-1) done
            if (q == 0 && tnext < ntiles)
                loadIdxTo(tnext, sIdx + (tp ^ 1) * 256);  // published by q=1 barrier
            if (q == NSEG - 1 && tnext < ntiles) {
                // L2 prefetch of next tile's chunk-0 gather (idxbn valid:
                // written at q==0, published by the q==1 barrier; NSEG>=3).
                int srow = idxbn[irow];
                if (srow >= 0)
                    asm volatile("prefetch.global.L2 [%0];"
                                 :: "l"(b0 + (size_t)srow * D + if4 * 16));
            }

            const uint32_t bufb = sHaddr + (q & 1) * 2048 * 4;
            const int k2base = q * 32;

            #pragma unroll
            for (int kg = 0; kg < 4; kg++) {
                const int ku = kg * 8;
                uint32_t a[2][4];
                #pragma unroll
                for (int ss = 0; ss < 2; ss++) {
                    int mrow = wr * 32 + ss * 16 + lmRowOff;
                    int ub   = ku + lmUnitOff;
                    uint32_t addr = bufb + (uint32_t)(mrow * 32 + (ub ^ ((mrow & 7) << 2))) * 4;
                    asm volatile("ldmatrix.sync.aligned.m8n8.x4.shared.b16 "
                                 "{%0,%1,%2,%3}, [%4];"
                                 : "=r"(a[ss][0]), "=r"(a[ss][1]),
                                   "=r"(a[ss][2]), "=r"(a[ss][3])
                                 : "r"(addr));
                }
                const uint32_t* pw = reinterpret_cast<const uint32_t*>(sWh);
                #pragma unroll
                for (int nt = 0; nt < 4; nt++) {
                    int c0 = (wc * 32 + nt * 8 + g) ^ (t << 3);
                    uint32_t b[2];
                    b[0] = pw[(k2base + ku + t) * 128 + c0];
                    b[1] = pw[(k2base + ku + t + 4) * 128 + c0];
                    mma16(acc[0][nt], a[0], b);
                    mma16(acc[1][nt], a[1], b);
                }
            }
        }

        // Epilogue: fp16 stores + stats (tail rows carry zero accs)
        #pragma unroll
        for (int ss = 0; ss < 2; ss++) {
            int row0 = base + wr * 32 + ss * 16 + g;
            #pragma unroll
            for (int nt = 0; nt < 4; nt++) {
                int col = wc * 32 + nt * 8 + 2 * t;
                __half* outp = (col < 64) ? g_coreh : g_gateh;
                int ocol = col & 63;
                if (row0 < R)
                    *reinterpret_cast<__half2*>(&outp[(size_t)row0 * D + ocol]) =
                        __floats2half2_rn(acc[ss][nt][0], acc[ss][nt][1]);
                if (row0 + 8 < R)
                    *reinterpret_cast<__half2*>(&outp[(size_t)(row0 + 8) * D + ocol]) =
                        __floats2half2_rn(acc[ss][nt][2], acc[ss][nt][3]);
                ssum[nt * 2 + 0] += acc[ss][nt][0] + acc[ss][nt][2];
                ssum[nt * 2 + 1] += acc[ss][nt][1] + acc[ss][nt][3];
                ssq[nt * 2 + 0]  += acc[ss][nt][0] * acc[ss][nt][0]
                                  + acc[ss][nt][2] * acc[ss][nt][2];
                ssq[nt * 2 + 1]  += acc[ss][nt][1] * acc[ss][nt][1]
                                  + acc[ss][nt][3] * acc[ss][nt][3];
            }
        }
    }

    #pragma unroll
    for (int j = 0; j < 8; j++) {
        int col = wc * 32 + (j >> 1) * 8 + 2 * t + (j & 1);
        int sb  = (col < 64) ? 0 : 128;
        int oc  = col & 63;
        atomicAdd(&sStat[sb + oc], ssum[j]);
        atomicAdd(&sStat[sb + 64 + oc], ssq[j]);
    }
    __syncthreads();
    atomicAdd(&g_stats[tid], sStat[tid]);
}

// ---------------------------------------------------------------------------
// Finalize BN scale/shift (1 block, 128 threads); self-zeroes g_stats.
// ---------------------------------------------------------------------------
__global__ void finalize_kernel(const float* __restrict__ gc, const float* __restrict__ bc,
                                const float* __restrict__ gg, const float* __restrict__ bg,
                                float invR)
{
    int t = threadIdx.x;
    if (t < 64) {
        float mean = g_stats[t] * invR;
        float var  = fmaxf(g_stats[64 + t] * invR - mean * mean, 0.f);
        float sc   = gc[t] * rsqrtf(var + 1e-5f);
        g_norm[t]      = sc;
        g_norm[64 + t] = bc[t] - mean * sc;
        g_stats[t] = 0.f;
        g_stats[64 + t] = 0.f;
    } else {
        int c = t - 64;
        float mean = g_stats[128 + c] * invR;
        float var  = fmaxf(g_stats[192 + c] * invR - mean * mean, 0.f);
        float sc   = gg[c] * rsqrtf(var + 1e-5f);
        g_norm[128 + c] = sc;
        g_norm[192 + c] = bg[c] - mean * sc;
        g_stats[128 + c] = 0.f;
        g_stats[192 + c] = 0.f;
    }
}

__device__ __forceinline__ float sigm(float x) { return 1.f / (1.f + __expf(-x)); }

__device__ __forceinline__ void unpack8(uint4 r, float o[8]) {
    __half2 h0 = *reinterpret_cast<__half2*>(&r.x);
    __half2 h1 = *reinterpret_cast<__half2*>(&r.y);
    __half2 h2 = *reinterpret_cast<__half2*>(&r.z);
    __half2 h3 = *reinterpret_cast<__half2*>(&r.w);
    float2 f0 = __half22float2(h0), f1 = __half22float2(h1);
    float2 f2 = __half22float2(h2), f3 = __half22float2(h3);
    o[0] = f0.x; o[1] = f0.y; o[2] = f1.x; o[3] = f1.y;
    o[4] = f2.x; o[5] = f2.y; o[6] = f3.x; o[7] = f3.y;
}

// ---------------------------------------------------------------------------
// BN + silu*sigmoid + vectorized atomic segment scatter (v4 red)
// ---------------------------------------------------------------------------
__global__ void apply_scatter_kernel(const int* __restrict__ seg, float* __restrict__ S, int R)
{
    int idx = blockIdx.x * blockDim.x + threadIdx.x;
    if (idx >= R * 8) return;
    int row = idx >> 3;
    int col = (idx & 7) * 8;
    int s = seg[row];                    // hoisted independent long-latency load
    uint4 cr = *reinterpret_cast<const uint4*>(g_coreh + (size_t)row * D + col);
    uint4 gr = *reinterpret_cast<const uint4*>(g_gateh + (size_t)row * D + col);

    float cs[8], gs[8];
    unpack8(cr, cs);
    unpack8(gr, gs);

    float m[8];
    #pragma unroll
    for (int j = 0; j < 8; j++) {
        int cc = col + j;
        float cn = cs[j] * g_norm[cc]       + g_norm[64 + cc];
        float gn = gs[j] * g_norm[128 + cc] + g_norm[192 + cc];
        m[j] = cn * sigm(cn) * sigm(gn);
    }
    float* dst = S + (size_t)s * D + col;
    asm volatile("red.global.add.v4.f32 [%0], {%1,%2,%3,%4};"
                 :: "l"(dst), "f"(m[0]), "f"(m[1]), "f"(m[2]), "f"(m[3]) : "memory");
    asm volatile("red.global.add.v4.f32 [%0], {%1,%2,%3,%4};"
                 :: "l"(dst + 4), "f"(m[4]), "f"(m[5]), "f"(m[6]), "f"(m[7]) : "memory");
}

// ---------------------------------------------------------------------------
// BN + silu*sigmoid + residual write (angle stage)
// ---------------------------------------------------------------------------
__global__ void apply_write_kernel(const float* __restrict__ angle, float* __restrict__ dst, int R)
{
    int idx = blockIdx.x * blockDim.x + threadIdx.x;
    if (idx >= R * 8) return;
    int row = idx >> 3;
    int col = (idx & 7) * 8;
    uint4 cr = *reinterpret_cast<const uint4*>(g_coreh + (size_t)row * D + col);
    uint4 gr = *reinterpret_cast<const uint4*>(g_gateh + (size_t)row * D + col);
    float4 a0 = *reinterpret_cast<const float4*>(angle + (size_t)row * D + col);
    float4 a1 = *reinterpret_cast<const float4*>(angle + (size_t)row * D + col + 4);

    float cs[8], gs[8];
    unpack8(cr, cs);
    unpack8(gr, gs);
    float av[8] = {a0.x, a0.y, a0.z, a0.w, a1.x, a1.y, a1.z, a1.w};

    float o[8];
    #pragma unroll
    for (int j = 0; j < 8; j++) {
        int cc = col + j;
        float cn = cs[j] * g_norm[cc]       + g_norm[64 + cc];
        float gn = gs[j] * g_norm[128 + cc] + g_norm[192 + cc];
        o[j] = cn * sigm(cn) * sigm(gn) + av[j];
    }
    *reinterpret_cast<float4*>(dst + (size_t)row * D + col) =
        make_float4(o[0], o[1], o[2], o[3]);
    *reinterpret_cast<float4*>(dst + (size_t)row * D + col + 4) =
        make_float4(o[4], o[5], o[6], o[7]);
}

// ---------------------------------------------------------------------------
// Row transform v3 (persistent, cp.async 3-slot ring with 2-deep prologue):
// S[tile,:] = S[tile,:] @ W(64x64) + resid.
// ---------------------------------------------------------------------------
__global__ void __launch_bounds__(256, 2) rowxform_mma(
    float* __restrict__ S, const float* __restrict__ W,
    const float* __restrict__ resid, int R)
{
    extern __shared__ float smem[];
    float* sW2 = smem;              // 64*64
    float* sX  = smem + 64 * 64;    // 3 * 64*64

    const int tid  = threadIdx.x;
    const int lane = tid & 31, wid = tid >> 5;
    const int wr = wid >> 1, wc = wid & 1;
    const int g = lane >> 2, t = lane & 3;

    for (int idx = tid; idx < 64 * 64; idx += 256) {
        int k = idx >> 6, c = idx & 63;
        sW2[k * 64 + (c ^ ((k & 3) << 3))] = f2tff(W[idx]);
    }

    // fetch mapping: thread covers row irow (0..63), 16 contiguous floats
    const int irow = tid >> 2;
    const int if4  = tid & 3;
    const int sw   = (irow & 7) << 2;

    auto issue = [&](int tile, int slot) {
        int grow = (tile << 6) + irow;
        int sz = (grow < R) ? 16 : 0;
        const float* src = S + (size_t)(grow < R ? grow : 0) * D + if4 * 16;
        float* dstb = sX + slot * 4096 + irow * 64;
        #pragma unroll
        for (int i = 0; i < 4; i++) {
            int f = if4 * 16 + i * 4;
            cpasync16(&dstb[f ^ sw], src + i * 4, sz);
        }
        asm volatile("cp.async.commit_group;");
    };

    const int ntiles = (R + 63) >> 6;
    int tile = blockIdx.x;
    if (tile < ntiles) issue(tile, 0);
    if (tile + gridDim.x < ntiles) issue(tile + gridDim.x, 1);

    unsigned it = 0;
    for (; tile < ntiles; tile += gridDim.x, it++) {
        const int base = tile << 6;
        const bool more1 = (tile + (int)gridDim.x) < ntiles;       // tile it+1 exists
        const bool more2 = (tile + 2 * (int)gridDim.x) < ntiles;   // tile it+2 exists

        if (more1) { asm volatile("cp.async.wait_group 1;"); }
        else       { asm volatile("cp.async.wait_group 0;"); }
        __syncthreads();   // publish tile it (+ sW2 on it==0); prove mma it-1 consumed
        if (more2) issue(tile + 2 * gridDim.x, (it + 2) % 3);

        const float* sB = sX + (it % 3) * 4096;

        float acc[4][4];
        #pragma unroll
        for (int nt = 0; nt < 4; nt++)
            #pragma unroll
            for (int i = 0; i < 4; i++) acc[nt][i] = 0.f;

        #pragma unroll
        for (int k0 = 0; k0 < 64; k0 += 8) {
            uint32_t a[4];
            int r0 = wr * 16 + g;
            int sw2 = (r0 & 7) << 2;
            const float* pa = &sB[r0 * 64];
            a[0] = __float_as_uint(pa[(k0 + t) ^ sw2]);
            a[1] = __float_as_uint(pa[8 * 64 + ((k0 + t) ^ sw2)]);
            a[2] = __float_as_uint(pa[(k0 + t + 4) ^ sw2]);
            a[3] = __float_as_uint(pa[8 * 64 + ((k0 + t + 4) ^ sw2)]);
            #pragma unroll
            for (int nt = 0; nt < 4; nt++) {
                int c0 = (wc * 32 + nt * 8 + g) ^ (t << 3);
                uint32_t b[2];
                b[0] = __float_as_uint(sW2[(k0 + t) * 64 + c0]);
                b[1] = __float_as_uint(sW2[(k0 + t + 4) * 64 + c0]);
                mma8(acc[nt], a, b);
            }
        }

        int row0 = base + wr * 16 + g;
        #pragma unroll
        for (int nt = 0; nt < 4; nt++) {
            int col = wc * 32 + nt * 8 + 2 * t;
            if (row0 < R) {
                float2 rr = *reinterpret_cast<const float2*>(&resid[(size_t)row0 * D + col]);
                *reinterpret_cast<float2*>(&S[(size_t)row0 * D + col]) =
                    make_float2(acc[nt][0] + rr.x, acc[nt][1] + rr.y);
            }
            if (row0 + 8 < R) {
                float2 rr = *reinterpret_cast<const float2*>(&resid[(size_t)(row0 + 8) * D + col]);
                *reinterpret_cast<float2*>(&S[(size_t)(row0 + 8) * D + col]) =
                    make_float2(acc[nt][2] + rr.x, acc[nt][3] + rr.y);
            }
        }
    }
}

// ---------------------------------------------------------------------------
// Host orchestration
// ---------------------------------------------------------------------------
extern "C" void kernel_launch(void* const* d_in, const int* in_sizes, int n_in,
                              void* d_out, int out_size)
{
    const bool dictOrder = (n_in >= 4) && (in_sizes[3] > 100000);

    const float *vfeat = (const float*)d_in[0];
    const float *efeat = (const float*)d_in[1];
    const float *afeat = (const float*)d_in[2];
    const float *WcA, *WgA, *WoA, *WcB, *WgB, *WoB, *WcC, *WgC;
    const float *gac, *bac, *gag, *bag, *gbc, *bbc, *gbg, *bbg, *gnc, *bnc, *gng, *bng;
    const int *eidx, *kidx, *iidx, *jidx;

    if (dictOrder) {
        eidx = (const int*)d_in[3];  kidx = (const int*)d_in[4];
        iidx = (const int*)d_in[5];  jidx = (const int*)d_in[6];
        WcA = (const float*)d_in[7];  WgA = (const float*)d_in[8];  WoA = (const float*)d_in[9];
        WcB = (const float*)d_in[10]; WgB = (const float*)d_in[11]; WoB = (const float*)d_in[12];
        WcC = (const float*)d_in[13]; WgC = (const float*)d_in[14];
        gac = (const float*)d_in[15]; gag = (const float*)d_in[16];
        gbc = (const float*)d_in[17]; gbg = (const float*)d_in[18];
        gnc = (const float*)d_in[19]; gng = (const float*)d_in[20];
        bac = (const float*)d_in[21]; bag = (const float*)d_in[22];
        bbc = (const float*)d_in[23]; bbg = (const float*)d_in[24];
        bnc = (const float*)d_in[25]; bng = (const float*)d_in[26];
    } else {
        WcA = (const float*)d_in[3];  WgA = (const float*)d_in[4];  WoA = (const float*)d_in[5];
        WcB = (const float*)d_in[6];  WgB = (const float*)d_in[7];  WoB = (const float*)d_in[8];
        WcC = (const float*)d_in[9];  WgC = (const float*)d_in[10];
        gac = (const float*)d_in[11]; bac = (const float*)d_in[12];
        gag = (const float*)d_in[13]; bag = (const float*)d_in[14];
        gbc = (const float*)d_in[15]; bbc = (const float*)d_in[16];
        gbg = (const float*)d_in[17]; bbg = (const float*)d_in[18];
        gnc = (const float*)d_in[19]; bnc = (const float*)d_in[20];
        gng = (const float*)d_in[21]; bng = (const float*)d_in[22];
        eidx = (const int*)d_in[23]; kidx = (const int*)d_in[24];
        iidx = (const int*)d_in[25]; jidx = (const int*)d_in[26];
    }

    const int N = in_sizes[0] / 64;
    const int E = in_sizes[1] / 64;
    const int T = in_sizes[2] / 64;
    const int* src = eidx;
    const int* dst = eidx + E;

    float* out  = (float*)d_out;
    float* vnew = out;                          // [N,64]
    float* enew = out + (size_t)N * 64;         // [E,64]
    float* anew = out + (size_t)(N + E) * 64;   // [T,64]

    float* stats_ptr = nullptr;
    cudaGetSymbolAddress((void**)&stats_ptr, g_stats);

    int dev = 0;  cudaGetDevice(&dev);
    int sm = 148; cudaDeviceGetAttribute(&sm, cudaDevAttrMultiProcessorCount, dev);

    // pass1 smem floats: K*64 (weights half2) + 2*2048 (fp16 ring) + 512 + 256
    const size_t smemA = (size_t)(192 * 64 + 2 * 2048 + 512 + 256) * 4; // 68,608 B
    const size_t smemB = (size_t)(256 * 64 + 2 * 2048 + 512 + 256) * 4; // 84,992 B
    cudaFuncSetAttribute(pass1_mma<192, 3>, cudaFuncAttributeMaxDynamicSharedMemorySize, (int)smemA);
    cudaFuncSetAttribute(pass1_mma<256, 4>, cudaFuncAttributeMaxDynamicSharedMemorySize, (int)smemB);

    // rowxform smem: (64*64 + 3*64*64) floats = 65,536 B
    const size_t smemR = (size_t)(4 * 64 * 64) * 4;
    cudaFuncSetAttribute(rowxform_mma, cudaFuncAttributeMaxDynamicSharedMemorySize, (int)smemR);

    // One contiguous memset for both segment-sum accumulators (vnew|enew),
    // and one for g_stats (finalize self-zeroes it between stages).
    cudaMemsetAsync(vnew, 0, (size_t)(N + E) * 64 * sizeof(float));
    cudaMemsetAsync(stats_ptr, 0, 256 * sizeof(float));

    // ---------------- Stage A: AtomConvCat ----------------
    pass1_mma<192, 3><<<sm * 2, 256, smemA>>>(
        vfeat, src, efeat, nullptr, vfeat, dst, nullptr, nullptr, WcA, WgA, E);
    finalize_kernel<<<1, 128>>>(gac, bac, gag, bag, 1.f / (float)E);
    apply_scatter_kernel<<<(E * 8 + 255) / 256, 256>>>(src, vnew, E);
    rowxform_mma<<<sm * 2, 256, smemR>>>(vnew, WoA, vfeat, N);

    // ---------------- Stage B: BondConvCat ----------------
    pass1_mma<256, 4><<<sm * 2, 256, smemB>>>(
        vnew, jidx, efeat, kidx, efeat, iidx, afeat, nullptr, WcB, WgB, T);
    finalize_kernel<<<1, 128>>>(gbc, bbc, gbg, bbg, 1.f / (float)T);
    apply_scatter_kernel<<<(T * 8 + 255) / 256, 256>>>(kidx, enew, T);
    rowxform_mma<<<sm * 2, 256, smemR>>>(enew, WoB, efeat, E);

    // ---------------- Stage C: AngleConvCat ----------------
    pass1_mma<256, 4><<<sm * 2, 256, smemB>>>(
        vnew, jidx, enew, kidx, enew, iidx, afeat, nullptr, WcC, WgC, T);
    finalize_kernel<<<1, 128>>>(gnc, bnc, gng, bng, 1.f / (float)T);
    apply_write_kernel<<<(T * 8 + 255) / 256, 256>>>(afeat, anew, T);
}